// round 1
// baseline (speedup 1.0000x reference)
#include <cuda_runtime.h>
#include <cuda_bf16.h>
#include <math.h>

// Problem constants (fixed by the reference setup)
#define BB 16
#define CC 256
#define HH 96
#define WW 128
#define HW (HH * WW)          // 12288
#define OUT_H 12
#define OUT_W 16
#define NN (OUT_H * OUT_W)    // 192
#define KH 8
#define KW 8
#define QQ 4
#define HIDDEN 128
#define TAU_INV 10.0f         // 1/tau1 = 1/tau2 = 10

// ---------------- device scratch (static, no allocation) ----------------
__device__ float g_qvals[BB * CC * QQ];   // soft-quantile values [b,c,q]
__device__ float g_scale[BB * CC];        // sigmoid attention scale
__device__ float g_da[CC];                // diag(Wa)
__device__ float g_db[CC];                // diag(Wb)
__device__ int   g_row[CC];               // per-row structure bits
__device__ int   g_flags;                 // bit0: both halves diagonal; bit1: Wb == 0
__device__ float g_M[BB * CC * CC];       // fallback fused matrix (4 MB)

__device__ __forceinline__ float sigmoidf_(float z) {
    return __fdividef(1.0f, 1.0f + __expf(-z));
}

// ---------------- structural analysis of wf ----------------
// wf is [C, 2C]. bit0 of g_row[c]: row c has zeros everywhere except (c,c),(c,C+c).
// bit1: the Wb half of row c is entirely zero.
__global__ void analyze1_kernel(const float* __restrict__ wf) {
    int c = blockIdx.x;          // 256 blocks
    int k = threadIdx.x;         // 512 threads
    float v = wf[c * (2 * CC) + k];
    if (k == c)       g_da[c] = v;
    if (k == CC + c)  g_db[c] = v;
    int is_off   = (k != c) && (k != CC + c);
    int ok_diag  = !(is_off && v != 0.0f);
    int wb_zero  = !((k >= CC) && v != 0.0f);
    int all_diag = __syncthreads_and(ok_diag);
    int all_wbz  = __syncthreads_and(wb_zero);
    if (k == 0) g_row[c] = (all_diag ? 1 : 0) | (all_wbz ? 2 : 0);
}

__global__ void analyze2_kernel() {
    int c = threadIdx.x;         // 1 block, 256 threads
    int r = g_row[c];
    int d = __syncthreads_and(r & 1);
    int z = __syncthreads_and(r & 2);
    if (c == 0) g_flags = (d ? 1 : 0) | (z ? 2 : 0);
}

// ---------------- pool + soft-rank + soft-quantile (only if Wb != 0) ----------------
__global__ void pool_rank_kernel(const float* __restrict__ x) {
    if (g_flags & 2) return;     // Wb == 0 -> scale never used
    __shared__ float s[NN];      // pooled values
    __shared__ float rr[NN];     // soft ranks
    __shared__ float2 red[256];

    int bc  = blockIdx.x;        // 4096 blocks, one (b,c) plane
    int tid = threadIdx.x;       // 256 threads

    // 8x8 average pool -> s[0..191]
    if (tid < NN) {
        int oh = tid >> 4, ow = tid & 15;
        const float* base = x + (size_t)bc * HW + oh * (KH * WW) + ow * KW;
        float acc = 0.0f;
        #pragma unroll
        for (int r = 0; r < KH; r++) {
            float4 a = *(const float4*)(base + r * WW);
            float4 b = *(const float4*)(base + r * WW + 4);
            acc += a.x + a.y + a.z + a.w + b.x + b.y + b.z + b.w;
        }
        s[tid] = acc * (1.0f / 64.0f);
    }
    __syncthreads();

    // soft rank: r_i = 1 + sum_j sigmoid((x_i - x_j)/tau1)
    if (tid < NN) {
        float xi = s[tid];
        float acc = 1.0f;
        #pragma unroll 4
        for (int j = 0; j < NN; j++) {
            acc += sigmoidf_((xi - s[j]) * TAU_INV);
        }
        rr[tid] = acc;
    }
    __syncthreads();

    // soft quantiles: softmax over -|r - t_q|/tau2, weighted sum of s
    const float quant[QQ] = {0.25f, 0.5f, 0.75f, 0.95f};
    for (int q = 0; q < QQ; q++) {
        float tq = 1.0f + quant[q] * (float)(NN - 1);
        float e = 0.0f, ex = 0.0f;
        if (tid < NN) {
            e  = __expf(-fabsf(rr[tid] - tq) * TAU_INV);
            ex = e * s[tid];
        }
        red[tid] = make_float2(e, ex);
        __syncthreads();
        for (int st = 128; st >= 1; st >>= 1) {
            if (tid < st) {
                float2 o = red[tid + st];
                red[tid].x += o.x;
                red[tid].y += o.y;
            }
            __syncthreads();
        }
        if (tid == 0) {
            g_qvals[bc * QQ + q] = red[0].y / red[0].x;
        }
        __syncthreads();
    }
}

// ---------------- conv1 + conv2 + sigmoid -> scale (only if Wb != 0) ----------------
__global__ void attn_kernel(const float* __restrict__ w1, const float* __restrict__ w2) {
    if (g_flags & 2) return;
    __shared__ float qv[CC * QQ];      // 1024
    __shared__ float ts[HIDDEN * QQ];  // 512
    int b = blockIdx.x, tid = threadIdx.x;

    for (int i = tid; i < CC * QQ; i += 256) qv[i] = g_qvals[b * CC * QQ + i];
    __syncthreads();

    for (int idx = tid; idx < HIDDEN * QQ; idx += 256) {
        int h = idx >> 2, q = idx & 3;
        float acc = 0.0f;
        #pragma unroll 4
        for (int c = 0; c < CC; c++) acc += w1[h * CC + c] * qv[c * QQ + q];
        ts[idx] = fmaxf(acc, 0.0f);
    }
    __syncthreads();

    int c = tid;
    float acc = 0.0f;
    #pragma unroll 4
    for (int k = 0; k < HIDDEN * QQ; k++) acc += ts[k] * w2[c * (HIDDEN * QQ) + k];
    g_scale[b * CC + c] = sigmoidf_(acc);
}

// ---------------- fast fused path: both halves diagonal ----------------
__global__ void fuse_fast_kernel(const float4* __restrict__ x4, float4* __restrict__ o4) {
    if (!(g_flags & 1)) return;
    int i = blockIdx.x * blockDim.x + threadIdx.x;          // over 12,582,912 float4
    int plane = i / (HW / 4);                                // b*C + c
    int c = plane & (CC - 1);
    float coeff = g_da[c] + g_db[c] * g_scale[plane];
    float4 v = x4[i];
    v.x *= coeff; v.y *= coeff; v.z *= coeff; v.w *= coeff;
    o4[i] = v;
}

// ---------------- general fallback: build M then batched GEMM ----------------
__global__ void buildM_kernel(const float* __restrict__ wf) {
    if (g_flags & 1) return;
    int bc = blockIdx.x;                 // b*C + c
    int b = bc >> 8, c = bc & 255;
    int k = threadIdx.x;                 // 256
    float wa = wf[c * (2 * CC) + k];
    float wb = wf[c * (2 * CC) + CC + k];
    g_M[(size_t)bc * CC + k] = wa + wb * g_scale[b * CC + k];
}

#define GT_C 64
#define GT_P 64
#define GT_K 16
__global__ void fuse_gemm_kernel(const float* __restrict__ x, float* __restrict__ out) {
    if (g_flags & 1) return;
    __shared__ float Ms[GT_C][GT_K];
    __shared__ float Xs[GT_K][GT_P];
    int b = blockIdx.z;
    int c0 = blockIdx.y * GT_C;
    int p0 = blockIdx.x * GT_P;
    int tid = threadIdx.x;
    int ty = tid >> 4, tx = tid & 15;    // 16x16 threads, 4x4 micro-tile
    float acc[4][4] = {};

    const float* Mb = g_M + (size_t)b * CC * CC;
    const float* xb = x + (size_t)b * CC * HW;

    for (int k0 = 0; k0 < CC; k0 += GT_K) {
        {
            int i = tid * 4;             // 1024 elems of M tile
            int row = i / GT_K, kk = i % GT_K;
            float4 v = *(const float4*)(Mb + (c0 + row) * CC + k0 + kk);
            Ms[row][kk] = v.x; Ms[row][kk + 1] = v.y; Ms[row][kk + 2] = v.z; Ms[row][kk + 3] = v.w;
            i = tid * 4;                 // 1024 elems of X tile
            row = i / GT_P; int col = i % GT_P;
            float4 u = *(const float4*)(xb + (k0 + row) * HW + p0 + col);
            Xs[row][col] = u.x; Xs[row][col + 1] = u.y; Xs[row][col + 2] = u.z; Xs[row][col + 3] = u.w;
        }
        __syncthreads();
        #pragma unroll
        for (int kk = 0; kk < GT_K; kk++) {
            float a[4], bx[4];
            #pragma unroll
            for (int i = 0; i < 4; i++) a[i] = Ms[ty * 4 + i][kk];
            #pragma unroll
            for (int j = 0; j < 4; j++) bx[j] = Xs[kk][tx * 4 + j];
            #pragma unroll
            for (int i = 0; i < 4; i++)
                #pragma unroll
                for (int j = 0; j < 4; j++)
                    acc[i][j] += a[i] * bx[j];
        }
        __syncthreads();
    }
    float* ob = out + (size_t)b * CC * HW;
    #pragma unroll
    for (int i = 0; i < 4; i++) {
        float4 v = make_float4(acc[i][0], acc[i][1], acc[i][2], acc[i][3]);
        *(float4*)(ob + (c0 + ty * 4 + i) * HW + p0 + tx * 4) = v;
    }
}

// ---------------- launch ----------------
extern "C" void kernel_launch(void* const* d_in, const int* in_sizes, int n_in,
                              void* d_out, int out_size) {
    const float* x  = (const float*)d_in[0];  // [B,C,H,W]
    const float* w1 = (const float*)d_in[1];  // [HIDDEN,C]
    const float* w2 = (const float*)d_in[2];  // [C,HIDDEN,Q]
    const float* wf = (const float*)d_in[3];  // [C,2C]
    float* out = (float*)d_out;

    analyze1_kernel<<<CC, 2 * CC>>>(wf);
    analyze2_kernel<<<1, CC>>>();
    pool_rank_kernel<<<BB * CC, 256>>>(x);
    attn_kernel<<<BB, 256>>>(w1, w2);
    buildM_kernel<<<BB * CC, CC>>>(wf);

    int n4 = BB * CC * HW / 4;                 // 12,582,912 float4
    fuse_fast_kernel<<<n4 / 256, 256>>>((const float4*)x, (float4*)out);

    dim3 gg(HW / GT_P, CC / GT_C, BB);
    fuse_gemm_kernel<<<gg, 256>>>(x, out);
}

// round 2
// speedup vs baseline: 1.2635x; 1.2635x over previous
#include <cuda_runtime.h>
#include <cuda_bf16.h>
#include <math.h>

// Problem constants (fixed by the reference setup)
#define BB 16
#define CC 256
#define HH 96
#define WW 128
#define HW (HH * WW)          // 12288
#define OUT_H 12
#define OUT_W 16
#define NN (OUT_H * OUT_W)    // 192
#define KH 8
#define KW 8
#define QQ 4
#define HIDDEN 128
#define TAU_INV 10.0f

// ---------------- device scratch (static, zero-initialized) ----------------
__device__ float g_qvals[BB * CC * QQ];
__device__ float g_scale[BB * CC];        // zero-init; only written when Wb != 0
__device__ float g_da[CC];
__device__ float g_db[CC];
__device__ int   g_viol;                  // bit0: NOT diagonal; bit1: Wb has nonzeros
__device__ unsigned g_done;               // fuse-kernel completion counter

__device__ __forceinline__ float sigmoidf_(float z) {
    return __fdividef(1.0f, 1.0f + __expf(-z));
}

// ---------------- structural analysis of wf (single kernel, atomicOr) ----------------
__global__ void analyze_kernel(const float* __restrict__ wf) {
    int c = blockIdx.x;          // 256
    int k = threadIdx.x;         // 512
    float v = wf[c * (2 * CC) + k];
    if (k == c)       g_da[c] = v;
    if (k == CC + c)  g_db[c] = v;
    int viol = 0;
    if ((k != c) && (k != CC + c) && v != 0.0f) viol |= 1;
    if ((k >= CC) && v != 0.0f)                 viol |= 2;
    viol = __syncthreads_or(viol);
    if (k == 0 && viol) atomicOr(&g_viol, viol);
}

// ---------------- pool + soft-rank + soft-quantile (only if Wb != 0) ----------------
__global__ void pool_rank_kernel(const float* __restrict__ x) {
    if ((g_viol & 2) == 0) return;           // Wb == 0 -> scale unused
    __shared__ float s[NN];
    __shared__ float rr[NN];
    __shared__ float2 red[256];

    int bc  = blockIdx.x;
    int tid = threadIdx.x;

    if (tid < NN) {
        int oh = tid >> 4, ow = tid & 15;
        const float* base = x + (size_t)bc * HW + oh * (KH * WW) + ow * KW;
        float acc = 0.0f;
        #pragma unroll
        for (int r = 0; r < KH; r++) {
            float4 a = *(const float4*)(base + r * WW);
            float4 b = *(const float4*)(base + r * WW + 4);
            acc += a.x + a.y + a.z + a.w + b.x + b.y + b.z + b.w;
        }
        s[tid] = acc * (1.0f / 64.0f);
    }
    __syncthreads();

    if (tid < NN) {
        float xi = s[tid];
        float acc = 1.0f;
        #pragma unroll 4
        for (int j = 0; j < NN; j++) acc += sigmoidf_((xi - s[j]) * TAU_INV);
        rr[tid] = acc;
    }
    __syncthreads();

    const float quant[QQ] = {0.25f, 0.5f, 0.75f, 0.95f};
    for (int q = 0; q < QQ; q++) {
        float tq = 1.0f + quant[q] * (float)(NN - 1);
        float e = 0.0f, ex = 0.0f;
        if (tid < NN) {
            e  = __expf(-fabsf(rr[tid] - tq) * TAU_INV);
            ex = e * s[tid];
        }
        red[tid] = make_float2(e, ex);
        __syncthreads();
        for (int st = 128; st >= 1; st >>= 1) {
            if (tid < st) {
                float2 o = red[tid + st];
                red[tid].x += o.x;
                red[tid].y += o.y;
            }
            __syncthreads();
        }
        if (tid == 0) g_qvals[bc * QQ + q] = red[0].y / red[0].x;
        __syncthreads();
    }
}

// ---------------- conv1 + conv2 + sigmoid -> scale (only if Wb != 0) ----------------
__global__ void attn_kernel(const float* __restrict__ w1, const float* __restrict__ w2) {
    if ((g_viol & 2) == 0) return;
    __shared__ float qv[CC * QQ];
    __shared__ float ts[HIDDEN * QQ];
    int b = blockIdx.x, tid = threadIdx.x;

    for (int i = tid; i < CC * QQ; i += 256) qv[i] = g_qvals[b * CC * QQ + i];
    __syncthreads();

    for (int idx = tid; idx < HIDDEN * QQ; idx += 256) {
        int h = idx >> 2, q = idx & 3;
        float acc = 0.0f;
        #pragma unroll 4
        for (int c = 0; c < CC; c++) acc += w1[h * CC + c] * qv[c * QQ + q];
        ts[idx] = fmaxf(acc, 0.0f);
    }
    __syncthreads();

    int c = tid;
    float acc = 0.0f;
    #pragma unroll 4
    for (int k = 0; k < HIDDEN * QQ; k++) acc += ts[k] * w2[c * (HIDDEN * QQ) + k];
    g_scale[b * CC + c] = sigmoidf_(acc);
}

// ---------------- single fused output kernel: fast diag path OR general GEMM ----------------
#define GT_C 64
#define GT_P 64
#define GT_K 16
// grid = 12288 blocks x 256 threads (same shape works for both paths)

__global__ void __launch_bounds__(256) fuse_kernel(const float* __restrict__ x,
                                                   const float* __restrict__ wf,
                                                   float* __restrict__ out) {
    __shared__ float Ms[GT_C][GT_K];
    __shared__ float Xs[GT_K][GT_P];

    int viol = g_viol;
    if (!(viol & 1)) {
        // ---- diagonal fast path: out = (da[c] + db[c]*scale[b,c]) * x ----
        int plane = blockIdx.x / 3;              // b*C + c
        int seg   = blockIdx.x % 3;              // 3 x 1024 float4 per plane (3072 total)
        int c = plane & (CC - 1);
        float coeff = g_da[c] + g_db[c] * g_scale[plane];
        const float4* src = (const float4*)x + (size_t)plane * (HW / 4) + seg * 1024 + threadIdx.x;
        float4*       dst = (float4*)out      + (size_t)plane * (HW / 4) + seg * 1024 + threadIdx.x;
        #pragma unroll
        for (int i = 0; i < 4; i++) {
            float4 v = src[i * 256];
            v.x *= coeff; v.y *= coeff; v.z *= coeff; v.w *= coeff;
            dst[i * 256] = v;
        }
    } else {
        // ---- general path: out[b] = M[b] @ x[b],  M = Wa + Wb*diag(scale[b]) on the fly ----
        int b  = blockIdx.x / 768;
        int r  = blockIdx.x % 768;
        int c0 = (r / 192) * GT_C;
        int p0 = (r % 192) * GT_P;
        int tid = threadIdx.x;
        int ty = tid >> 4, tx = tid & 15;
        float acc[4][4] = {};

        const float* xb = x + (size_t)b * CC * HW;
        const float* sb = g_scale + b * CC;

        for (int k0 = 0; k0 < CC; k0 += GT_K) {
            {
                // M tile: 64x16, each thread 4 contiguous k
                int row = tid >> 2;              // 0..63
                int kk  = (tid & 3) * 4;         // 0,4,8,12
                int cr  = c0 + row;
                float4 wa = *(const float4*)(wf + cr * (2 * CC) + k0 + kk);
                float4 wb = *(const float4*)(wf + cr * (2 * CC) + CC + k0 + kk);
                float4 sc = *(const float4*)(sb + k0 + kk);
                Ms[row][kk + 0] = wa.x + wb.x * sc.x;
                Ms[row][kk + 1] = wa.y + wb.y * sc.y;
                Ms[row][kk + 2] = wa.z + wb.z * sc.z;
                Ms[row][kk + 3] = wa.w + wb.w * sc.w;
                // X tile: 16x64
                int i = tid * 4;
                int xr = i / GT_P, xc = i % GT_P;
                float4 u = *(const float4*)(xb + (k0 + xr) * HW + p0 + xc);
                Xs[xr][xc] = u.x; Xs[xr][xc + 1] = u.y; Xs[xr][xc + 2] = u.z; Xs[xr][xc + 3] = u.w;
            }
            __syncthreads();
            #pragma unroll
            for (int kk = 0; kk < GT_K; kk++) {
                float a[4], bx[4];
                #pragma unroll
                for (int i = 0; i < 4; i++) a[i] = Ms[ty * 4 + i][kk];
                #pragma unroll
                for (int j = 0; j < 4; j++) bx[j] = Xs[kk][tx * 4 + j];
                #pragma unroll
                for (int i = 0; i < 4; i++)
                    #pragma unroll
                    for (int j = 0; j < 4; j++)
                        acc[i][j] += a[i] * bx[j];
            }
            __syncthreads();
        }
        float* ob = out + (size_t)b * CC * HW;
        #pragma unroll
        for (int i = 0; i < 4; i++) {
            float4 v = make_float4(acc[i][0], acc[i][1], acc[i][2], acc[i][3]);
            *(float4*)(ob + (c0 + ty * 4 + i) * HW + p0 + tx * 4) = v;
        }
    }

    // last finishing block resets the per-call flags for the next graph replay
    if (threadIdx.x == 0) {
        if (atomicAdd(&g_done, 1u) == (unsigned)(gridDim.x - 1)) {
            g_viol = 0;
            g_done = 0;
        }
    }
}

// ---------------- launch ----------------
extern "C" void kernel_launch(void* const* d_in, const int* in_sizes, int n_in,
                              void* d_out, int out_size) {
    const float* x  = (const float*)d_in[0];
    const float* w1 = (const float*)d_in[1];
    const float* w2 = (const float*)d_in[2];
    const float* wf = (const float*)d_in[3];
    float* out = (float*)d_out;

    analyze_kernel<<<CC, 2 * CC>>>(wf);
    pool_rank_kernel<<<BB * CC, 256>>>(x);
    attn_kernel<<<BB, 256>>>(w1, w2);
    fuse_kernel<<<BB * CC * 3, 256>>>(x, wf, out);
}

// round 3
// speedup vs baseline: 1.3030x; 1.0313x over previous
#include <cuda_runtime.h>
#include <cuda_bf16.h>
#include <math.h>

#define BB 16
#define CC 256
#define HH 96
#define WW 128
#define HW (HH * WW)          // 12288
#define OUT_H 12
#define OUT_W 16
#define NN (OUT_H * OUT_W)    // 192
#define KH 8
#define KW 8
#define QQ 4
#define HIDDEN 128
#define TAU_INV 10.0f

// ---------------- device scratch (static, zero-initialized) ----------------
__device__ float g_scale[BB * CC];        // zero-init; only written when Wb != 0
__device__ float g_da[CC];
__device__ float g_db[CC];
__device__ int   g_viol;                  // bit0: NOT diagonal; bit1: Wb has nonzeros
__device__ unsigned g_done;               // fuse-kernel completion counter

__device__ __forceinline__ float sigmoidf_(float z) {
    return __fdividef(1.0f, 1.0f + __expf(-z));
}

// ---------------- structural analysis of wf ----------------
__global__ void analyze_kernel(const float* __restrict__ wf) {
    int c = blockIdx.x;          // 256
    int k = threadIdx.x;         // 512
    float v = wf[c * (2 * CC) + k];
    if (k == c)       g_da[c] = v;
    if (k == CC + c)  g_db[c] = v;
    int viol = 0;
    if ((k != c) && (k != CC + c) && v != 0.0f) viol |= 1;
    if ((k >= CC) && v != 0.0f)                 viol |= 2;
    viol = __syncthreads_or(viol);
    if (k == 0 && viol) atomicOr(&g_viol, viol);
}

// ---------------- merged scale pipeline (only runs when Wb != 0) ----------------
// grid = 16 (one block per batch), 256 threads. Computes pool -> soft-rank ->
// soft-quantile for all 256 channels serially, keeps qvals in shared, then
// does conv1+relu+conv2+sigmoid -> g_scale. Slow path only; correctness-grade.
__global__ void scale_kernel(const float* __restrict__ x,
                             const float* __restrict__ w1,
                             const float* __restrict__ w2) {
    if ((g_viol & 2) == 0) return;           // Wb == 0 -> scale unused
    __shared__ float s[NN];
    __shared__ float rr[NN];
    __shared__ float2 red[256];
    __shared__ float qv[CC * QQ];            // quantiles for this batch
    __shared__ float ts[HIDDEN * QQ];

    int b   = blockIdx.x;
    int tid = threadIdx.x;
    const float quant[QQ] = {0.25f, 0.5f, 0.75f, 0.95f};

    for (int c = 0; c < CC; c++) {
        int bc = b * CC + c;
        // 8x8 average pool
        if (tid < NN) {
            int oh = tid >> 4, ow = tid & 15;
            const float* base = x + (size_t)bc * HW + oh * (KH * WW) + ow * KW;
            float acc = 0.0f;
            #pragma unroll
            for (int r = 0; r < KH; r++) {
                float4 a = *(const float4*)(base + r * WW);
                float4 bb = *(const float4*)(base + r * WW + 4);
                acc += a.x + a.y + a.z + a.w + bb.x + bb.y + bb.z + bb.w;
            }
            s[tid] = acc * (1.0f / 64.0f);
        }
        __syncthreads();
        // soft rank
        if (tid < NN) {
            float xi = s[tid];
            float acc = 1.0f;
            #pragma unroll 4
            for (int j = 0; j < NN; j++) acc += sigmoidf_((xi - s[j]) * TAU_INV);
            rr[tid] = acc;
        }
        __syncthreads();
        // soft quantiles
        for (int q = 0; q < QQ; q++) {
            float tq = 1.0f + quant[q] * (float)(NN - 1);
            float e = 0.0f, ex = 0.0f;
            if (tid < NN) {
                e  = __expf(-fabsf(rr[tid] - tq) * TAU_INV);
                ex = e * s[tid];
            }
            red[tid] = make_float2(e, ex);
            __syncthreads();
            for (int st = 128; st >= 1; st >>= 1) {
                if (tid < st) {
                    float2 o = red[tid + st];
                    red[tid].x += o.x;
                    red[tid].y += o.y;
                }
                __syncthreads();
            }
            if (tid == 0) qv[c * QQ + q] = red[0].y / red[0].x;
            __syncthreads();
        }
    }

    // conv1 (1x1) + relu
    for (int idx = tid; idx < HIDDEN * QQ; idx += 256) {
        int h = idx >> 2, q = idx & 3;
        float acc = 0.0f;
        #pragma unroll 4
        for (int c = 0; c < CC; c++) acc += w1[h * CC + c] * qv[c * QQ + q];
        ts[idx] = fmaxf(acc, 0.0f);
    }
    __syncthreads();
    // conv2 (1,Q) + sigmoid
    {
        int c = tid;
        float acc = 0.0f;
        #pragma unroll 4
        for (int k = 0; k < HIDDEN * QQ; k++) acc += ts[k] * w2[c * (HIDDEN * QQ) + k];
        g_scale[b * CC + c] = sigmoidf_(acc);
    }
}

// ---------------- single fused output kernel ----------------
#define GT_C 64
#define GT_P 64
#define GT_K 16

__global__ void __launch_bounds__(256, 6) fuse_kernel(const float* __restrict__ x,
                                                      const float* __restrict__ wf,
                                                      float* __restrict__ out) {
    __shared__ float Ms[GT_C][GT_K];
    __shared__ float Xs[GT_K][GT_P];

    int viol = g_viol;
    if (!(viol & 1)) {
        // diagonal fast path: out = (da[c] + db[c]*scale[b,c]) * x
        int plane = blockIdx.x / 3;              // b*C + c
        int seg   = blockIdx.x % 3;
        int c = plane & (CC - 1);
        float coeff = g_da[c] + g_db[c] * g_scale[plane];
        const float4* src = (const float4*)x + (size_t)plane * (HW / 4) + seg * 1024 + threadIdx.x;
        float4*       dst = (float4*)out      + (size_t)plane * (HW / 4) + seg * 1024 + threadIdx.x;
        float4 v0 = src[0];
        float4 v1 = src[256];
        float4 v2 = src[512];
        float4 v3 = src[768];
        v0.x *= coeff; v0.y *= coeff; v0.z *= coeff; v0.w *= coeff;
        v1.x *= coeff; v1.y *= coeff; v1.z *= coeff; v1.w *= coeff;
        v2.x *= coeff; v2.y *= coeff; v2.z *= coeff; v2.w *= coeff;
        v3.x *= coeff; v3.y *= coeff; v3.z *= coeff; v3.w *= coeff;
        dst[0]   = v0;
        dst[256] = v1;
        dst[512] = v2;
        dst[768] = v3;
    } else {
        // general path: out[b] = (Wa + Wb*diag(scale[b])) @ x[b], M built on the fly
        int b  = blockIdx.x / 768;
        int r  = blockIdx.x % 768;
        int c0 = (r / 192) * GT_C;
        int p0 = (r % 192) * GT_P;
        int tid = threadIdx.x;
        int ty = tid >> 4, tx = tid & 15;
        float acc[4][4] = {};

        const float* xb = x + (size_t)b * CC * HW;
        const float* sb = g_scale + b * CC;

        for (int k0 = 0; k0 < CC; k0 += GT_K) {
            {
                int row = tid >> 2;
                int kk  = (tid & 3) * 4;
                int cr  = c0 + row;
                float4 wa = *(const float4*)(wf + cr * (2 * CC) + k0 + kk);
                float4 wb = *(const float4*)(wf + cr * (2 * CC) + CC + k0 + kk);
                float4 sc = *(const float4*)(sb + k0 + kk);
                Ms[row][kk + 0] = wa.x + wb.x * sc.x;
                Ms[row][kk + 1] = wa.y + wb.y * sc.y;
                Ms[row][kk + 2] = wa.z + wb.z * sc.z;
                Ms[row][kk + 3] = wa.w + wb.w * sc.w;
                int i = tid * 4;
                int xr = i / GT_P, xc = i % GT_P;
                float4 u = *(const float4*)(xb + (k0 + xr) * HW + p0 + xc);
                Xs[xr][xc] = u.x; Xs[xr][xc + 1] = u.y; Xs[xr][xc + 2] = u.z; Xs[xr][xc + 3] = u.w;
            }
            __syncthreads();
            #pragma unroll
            for (int kk = 0; kk < GT_K; kk++) {
                float a[4], bx[4];
                #pragma unroll
                for (int i = 0; i < 4; i++) a[i] = Ms[ty * 4 + i][kk];
                #pragma unroll
                for (int j = 0; j < 4; j++) bx[j] = Xs[kk][tx * 4 + j];
                #pragma unroll
                for (int i = 0; i < 4; i++)
                    #pragma unroll
                    for (int j = 0; j < 4; j++)
                        acc[i][j] += a[i] * bx[j];
            }
            __syncthreads();
        }
        float* ob = out + (size_t)b * CC * HW;
        #pragma unroll
        for (int i = 0; i < 4; i++) {
            float4 v = make_float4(acc[i][0], acc[i][1], acc[i][2], acc[i][3]);
            *(float4*)(ob + (c0 + ty * 4 + i) * HW + p0 + tx * 4) = v;
        }
    }

    // last finishing block resets per-call flags for the next graph replay
    if (threadIdx.x == 0) {
        if (atomicAdd(&g_done, 1u) == (unsigned)(gridDim.x - 1)) {
            g_viol = 0;
            g_done = 0;
        }
    }
}

// ---------------- launch ----------------
extern "C" void kernel_launch(void* const* d_in, const int* in_sizes, int n_in,
                              void* d_out, int out_size) {
    const float* x  = (const float*)d_in[0];
    const float* w1 = (const float*)d_in[1];
    const float* w2 = (const float*)d_in[2];
    const float* wf = (const float*)d_in[3];
    float* out = (float*)d_out;

    analyze_kernel<<<CC, 2 * CC>>>(wf);
    scale_kernel<<<BB, 256>>>(x, w1, w2);
    fuse_kernel<<<BB * CC * 3, 256>>>(x, wf, out);
}